// round 12
// baseline (speedup 1.0000x reference)
#include <cuda_runtime.h>
#include <cuda_bf16.h>
#include <cstdint>
#include <math.h>

// Problem constants
#define NN 50000
#define EE 600000
#define DD 128
#define LL 3
#define GTILES 782            // ceil(50000/64)
#define NPAD (GTILES * 64)    // 50048
#define SMP 136               // smem row stride (bf16): conflict-free ldmatrix
#define CAP 64                // fixed bucket capacity per node (P(deg>64) ~ 0)

// ---------------- device scratch (static; no runtime alloc) ----------------
__device__ float g_B1[NPAD * DD];   // x  / y2
__device__ float g_B2[NPAD * DD];   // y  / h
__device__ float g_statS[9][DD];    // stage = layer*3 + {gemm1, gemm2, zstats}
__device__ float g_statQ[9][DD];
__device__ __nv_bfloat16 g_bthi[LL * 2 * DD * DD];
__device__ __nv_bfloat16 g_btlo[LL * 2 * DD * DD];
__device__ int  g_curArr[NN];       // slot counter -> degree after fill
__device__ int2 g_ssw[NN * CAP];    // (src, w bits), bucketed per dst

// ---------------- warp-mma helpers ----------------
__device__ __forceinline__ uint32_t smem_u32(const void* p) {
    uint32_t a;
    asm("{ .reg .u64 t; cvta.to.shared.u64 t, %1; cvt.u32.u64 %0, t; }" : "=r"(a) : "l"(p));
    return a;
}
__device__ __forceinline__ void ldsm_x4(uint32_t* r, uint32_t addr) {
    asm volatile("ldmatrix.sync.aligned.m8n8.x4.shared.b16 {%0,%1,%2,%3}, [%4];"
                 : "=r"(r[0]), "=r"(r[1]), "=r"(r[2]), "=r"(r[3]) : "r"(addr));
}
__device__ __forceinline__ void mma_bf16(float* d, const uint32_t* a, const uint32_t* b) {
    asm volatile("mma.sync.aligned.m16n8k16.row.col.f32.bf16.bf16.f32 "
                 "{%0,%1,%2,%3}, {%4,%5,%6,%7}, {%8,%9}, {%0,%1,%2,%3};"
                 : "+f"(d[0]), "+f"(d[1]), "+f"(d[2]), "+f"(d[3])
                 : "r"(a[0]), "r"(a[1]), "r"(a[2]), "r"(a[3]),
                   "r"(b[0]), "r"(b[1]));
}

// BN affine from raw stats: a = g*rsqrt(var+eps), c = b - mean*a
__device__ __forceinline__ void affine_from_stats(
    const float* __restrict__ cs, const float* __restrict__ cq,
    const float* __restrict__ g, const float* __restrict__ b,
    float* sA, float* sC, int t)
{
    if (t < DD) {
        const float invN = 1.f / (float)NN;
        float mean = cs[t] * invN;
        float var  = cq[t] * invN - mean * mean;
        float a = g[t] * rsqrtf(var + 1e-5f);
        sA[t] = a;
        sC[t] = b[t] - mean * a;
    }
}

// ---------------- setup: zero counters/stats + weight hi/lo transpose ----------------
__global__ void setup_kernel(const float* __restrict__ W0s, const float* __restrict__ W1s,
                             __nv_bfloat16* __restrict__ bhi, __nv_bfloat16* __restrict__ blo,
                             int* cur, float* statS, float* statQ)
{
    int idx = blockIdx.x * blockDim.x + threadIdx.x;
    if (idx < NN) cur[idx] = 0;
    if (idx < 9 * DD) { statS[idx] = 0.f; statQ[idx] = 0.f; }
    if (idx < 6 * DD * DD) {
        int m2 = idx >> 14, r = idx & 16383;
        int k = r >> 7, n = r & 127;
        int layer = m2 >> 1, which = m2 & 1;
        const float* W = (which ? W1s : W0s) + layer * DD * DD;
        float v = W[r];
        __nv_bfloat16 h = __float2bfloat16(v);
        __nv_bfloat16 lo = __float2bfloat16(v - __bfloat162float(h));
        bhi[m2 * DD * DD + n * DD + k] = h;
        blo[m2 * DD * DD + n * DD + k] = lo;
    }
}

// Bucketed fill: slot via atomicAdd; no scan needed.
__global__ void fill_kernel(const int* __restrict__ src, const int* __restrict__ dst,
                            const float* __restrict__ w, int* cur, int2* ssw) {
    int e = blockIdx.x * blockDim.x + threadIdx.x;
    if (e >= EE) return;
    int d = __ldg(dst + e);
    int slot = atomicAdd(cur + d, 1);
    if (slot < CAP)
        ssw[d * CAP + slot] = make_int2(__ldg(src + e), __float_as_int(__ldg(w + e)));
}

// x[d] = h[d] + sum_e w*h[src]. Warp per node; 2-way unrolled edge loop.
__global__ void __launch_bounds__(256) gather_kernel(
    const float* __restrict__ hprev, const int* __restrict__ cur,
    const int2* __restrict__ ssw, float* __restrict__ x)
{
    int d = (blockIdx.x * blockDim.x + threadIdx.x) >> 5;
    int l = threadIdx.x & 31;
    if (d >= NN) return;
    int deg = min(__ldg(cur + d), CAP);
    int st  = d * CAP;
    float4 acc0 = *(const float4*)(hprev + (size_t)d * DD + l * 4);
    float4 acc1 = make_float4(0.f, 0.f, 0.f, 0.f);
    int j = 0;
    for (; j + 2 <= deg; j += 2) {
        int2 p0 = __ldg(ssw + st + j);
        int2 p1 = __ldg(ssw + st + j + 1);
        float4 h0 = *(const float4*)(hprev + (size_t)p0.x * DD + l * 4);
        float4 h1 = *(const float4*)(hprev + (size_t)p1.x * DD + l * 4);
        float w0 = __int_as_float(p0.y), w1 = __int_as_float(p1.y);
        acc0.x = fmaf(w0, h0.x, acc0.x); acc1.x = fmaf(w1, h1.x, acc1.x);
        acc0.y = fmaf(w0, h0.y, acc0.y); acc1.y = fmaf(w1, h1.y, acc1.y);
        acc0.z = fmaf(w0, h0.z, acc0.z); acc1.z = fmaf(w1, h1.z, acc1.z);
        acc0.w = fmaf(w0, h0.w, acc0.w); acc1.w = fmaf(w1, h1.w, acc1.w);
    }
    if (j < deg) {
        int2 p = __ldg(ssw + st + j);
        float we = __int_as_float(p.y);
        float4 hv = *(const float4*)(hprev + (size_t)p.x * DD + l * 4);
        acc0.x = fmaf(we, hv.x, acc0.x);
        acc0.y = fmaf(we, hv.y, acc0.y);
        acc0.z = fmaf(we, hv.z, acc0.z);
        acc0.w = fmaf(we, hv.w, acc0.w);
    }
    acc0.x += acc1.x; acc0.y += acc1.y; acc0.z += acc1.z; acc0.w += acc1.w;
    *(float4*)(x + (size_t)d * DD + l * 4) = acc0;
}

// C[64-tile,128] = act(A) @ W, mma.sync bf16 hi/lo 3-pass, fused column stats.
// 512 threads / 16 warps; warp tile 16(M) x 32(N).
__global__ void __launch_bounds__(512, 2) gemm_mma_kernel(
    const float* __restrict__ A,
    const __nv_bfloat16* __restrict__ Bhi, const __nv_bfloat16* __restrict__ Blo,
    float* __restrict__ C,
    const float* __restrict__ csIn, const float* __restrict__ cqIn,
    const float* __restrict__ bng, const float* __restrict__ bnb, int useAffine,
    float* __restrict__ statS, float* __restrict__ statQ)
{
    extern __shared__ __align__(16) char dyn[];
    __nv_bfloat16* sAhi = (__nv_bfloat16*)dyn;
    __nv_bfloat16* sAlo = sAhi + 64 * SMP;
    __nv_bfloat16* sBhi = sAlo + 64 * SMP;
    __nv_bfloat16* sBlo = sBhi + 128 * SMP;
    __shared__ float colS[DD], colQ[DD];
    __shared__ float sAf[DD], sCf[DD];

    const int t = threadIdx.x, w = t >> 5, l = t & 31;
    const int mBase = blockIdx.x * 64;

    if (t < DD) { colS[t] = 0.f; colQ[t] = 0.f; }
    if (useAffine) {
        affine_from_stats(csIn, cqIn, bng, bnb, sAf, sCf, t);
        __syncthreads();
    }

    // stage A: 64 rows, 16 warps -> 4 iterations
    float4 aa, cc;
    if (useAffine) { aa = ((const float4*)sAf)[l]; cc = ((const float4*)sCf)[l]; }
#pragma unroll
    for (int it = 0; it < 4; it++) {
        int row = it * 16 + w;
        float4 v = ((const float4*)(A + (size_t)(mBase + row) * DD))[l];
        if (useAffine) {
            v.x = fmaxf(fmaf(v.x, aa.x, cc.x), 0.f);
            v.y = fmaxf(fmaf(v.y, aa.y, cc.y), 0.f);
            v.z = fmaxf(fmaf(v.z, aa.z, cc.z), 0.f);
            v.w = fmaxf(fmaf(v.w, aa.w, cc.w), 0.f);
        }
        __nv_bfloat162 h01 = __floats2bfloat162_rn(v.x, v.y);
        __nv_bfloat162 h23 = __floats2bfloat162_rn(v.z, v.w);
        __nv_bfloat162 l01 = __floats2bfloat162_rn(v.x - __low2float(h01), v.y - __high2float(h01));
        __nv_bfloat162 l23 = __floats2bfloat162_rn(v.z - __low2float(h23), v.w - __high2float(h23));
        int off = row * SMP + l * 4;
        *(uint2*)(sAhi + off) = make_uint2(*(uint32_t*)&h01, *(uint32_t*)&h23);
        *(uint2*)(sAlo + off) = make_uint2(*(uint32_t*)&l01, *(uint32_t*)&l23);
    }
    // stage B: 128 n-rows, 16 warps -> 8 iterations
#pragma unroll
    for (int it = 0; it < 8; it++) {
        int row = it * 16 + w;
        uint2 hv = ((const uint2*)(Bhi + (size_t)row * DD))[l];
        uint2 lv = ((const uint2*)(Blo + (size_t)row * DD))[l];
        int off = row * SMP + l * 4;
        *(uint2*)(sBhi + off) = hv;
        *(uint2*)(sBlo + off) = lv;
    }
    __syncthreads();

    // warp tile: 16(M) x 32(N); 4 n-subtiles of n8
    const int wm = (w >> 2) * 16;
    const int wn = (w & 3) * 32;
    float acc[4][4];
#pragma unroll
    for (int i = 0; i < 4; i++)
#pragma unroll
        for (int j = 0; j < 4; j++) acc[i][j] = 0.f;

    const int arow = wm + (l & 15);
    const int acol = (l >> 4) << 3;
    const int browb = wn + ((l >> 4) & 1) * 8 + (l & 7);   // paired-n ldsm.x4
    const int bcol  = ((l >> 3) & 1) << 3;

#pragma unroll
    for (int pass = 0; pass < 3; pass++) {
        const __nv_bfloat16* pA = (pass == 2) ? sAlo : sAhi;
        const __nv_bfloat16* pB = (pass == 1) ? sBlo : sBhi;
#pragma unroll
        for (int kc = 0; kc < 8; kc++) {
            const int k0 = kc * 16;
            uint32_t afr[4];
            ldsm_x4(afr, smem_u32(pA + arow * SMP + k0 + acol));
#pragma unroll
            for (int sn2 = 0; sn2 < 2; sn2++) {
                uint32_t bfr[4];
                ldsm_x4(bfr, smem_u32(pB + (browb + sn2 * 16) * SMP + k0 + bcol));
                mma_bf16(acc[sn2 * 2 + 0], afr, bfr + 0);
                mma_bf16(acc[sn2 * 2 + 1], afr, bfr + 2);
            }
        }
    }

    // epilogue: store + fused column stats (mask pad rows)
    const int g = l >> 2, tq = l & 3;
    const int row0 = mBase + wm + g;
    const float m0 = (row0 < NN) ? 1.f : 0.f;
    const float m1 = (row0 + 8 < NN) ? 1.f : 0.f;
#pragma unroll
    for (int sn = 0; sn < 4; sn++) {
        int col = wn + sn * 8 + tq * 2;
        float* p0 = C + (size_t)row0 * DD + col;
        *(float2*)p0            = make_float2(acc[sn][0], acc[sn][1]);
        *(float2*)(p0 + 8 * DD) = make_float2(acc[sn][2], acc[sn][3]);
        float v0 = m0 * acc[sn][0], v1 = m0 * acc[sn][1];
        float v2 = m1 * acc[sn][2], v3 = m1 * acc[sn][3];
        float cs0 = v0 + v2, cs1 = v1 + v3;
        float cq0 = v0 * v0 + v2 * v2, cq1 = v1 * v1 + v3 * v3;
#pragma unroll
        for (int dlt = 16; dlt >= 4; dlt >>= 1) {
            cs0 += __shfl_down_sync(0xffffffffu, cs0, dlt);
            cs1 += __shfl_down_sync(0xffffffffu, cs1, dlt);
            cq0 += __shfl_down_sync(0xffffffffu, cq0, dlt);
            cq1 += __shfl_down_sync(0xffffffffu, cq1, dlt);
        }
        if (l < 4) {
            int c0 = wn + sn * 8 + l * 2;
            atomicAdd(&colS[c0], cs0);  atomicAdd(&colS[c0 + 1], cs1);
            atomicAdd(&colQ[c0], cq0);  atomicAdd(&colQ[c0 + 1], cq1);
        }
    }
    __syncthreads();
    if (t < DD) {
        atomicAdd(statS + t, colS[t]);
        atomicAdd(statQ + t, colQ[t]);
    }
}

// stats of relu(bn2(y2)); bn2 affine from raw stats at entry.
__global__ void __launch_bounds__(256) zstats_kernel(const float* __restrict__ y2,
                                                     const float* __restrict__ cs2,
                                                     const float* __restrict__ cq2,
                                                     const float* __restrict__ bn2g,
                                                     const float* __restrict__ bn2b,
                                                     float* __restrict__ cs,
                                                     float* __restrict__ cq)
{
    __shared__ float shS[8][DD];
    __shared__ float shQ[8][DD];
    __shared__ float sAf[DD], sCf[DD];
    const int t = threadIdx.x;
    const int c4 = (t & 31) * 4;
    const int rg = t >> 5;
    affine_from_stats(cs2, cq2, bn2g, bn2b, sAf, sCf, t);
    __syncthreads();
    float4 a = *(const float4*)(sAf + c4);
    float4 c = *(const float4*)(sCf + c4);
    float4 s = make_float4(0.f, 0.f, 0.f, 0.f), q = make_float4(0.f, 0.f, 0.f, 0.f);
    for (int m = blockIdx.x * 8 + rg; m < NN; m += gridDim.x * 8) {
        float4 v = *(const float4*)(y2 + (size_t)m * DD + c4);
        v.x = fmaxf(fmaf(v.x, a.x, c.x), 0.f);
        v.y = fmaxf(fmaf(v.y, a.y, c.y), 0.f);
        v.z = fmaxf(fmaf(v.z, a.z, c.z), 0.f);
        v.w = fmaxf(fmaf(v.w, a.w, c.w), 0.f);
        s.x += v.x; s.y += v.y; s.z += v.z; s.w += v.w;
        q.x += v.x * v.x; q.y += v.y * v.y; q.z += v.z * v.z; q.w += v.w * v.w;
    }
    *(float4*)&shS[rg][c4] = s;
    *(float4*)&shQ[rg][c4] = q;
    __syncthreads();
    if (t < DD) {
        float ts = 0.f, tqv = 0.f;
#pragma unroll
        for (int i = 0; i < 8; i++) { ts += shS[i][t]; tqv += shQ[i][t]; }
        atomicAdd(cs + t, ts);
        atomicAdd(cq + t, tqv);
    }
}

// out = bn3(relu(bn2(y2))) (+ optional relu). Affines from raw stats at entry.
__global__ void __launch_bounds__(256) apply_kernel(
    const float* __restrict__ y2,
    const float* __restrict__ cs2, const float* __restrict__ cq2,
    const float* __restrict__ bn2g, const float* __restrict__ bn2b,
    const float* __restrict__ cs3, const float* __restrict__ cq3,
    const float* __restrict__ bn3g, const float* __restrict__ bn3b,
    float* __restrict__ out, int doRelu)
{
    __shared__ float sA2[DD], sC2[DD], sA3[DD], sC3[DD];
    const int t = threadIdx.x;
    affine_from_stats(cs2, cq2, bn2g, bn2b, sA2, sC2, t);
    affine_from_stats(cs3, cq3, bn3g, bn3b, sA3, sC3, t);
    __syncthreads();
    int gid = blockIdx.x * blockDim.x + t;
    if (gid >= NN * (DD / 4)) return;
    int col4 = (gid & (DD / 4 - 1)) << 2;
    float4 v = ((const float4*)y2)[gid];
    float4 A2 = *(const float4*)(sA2 + col4);
    float4 C2 = *(const float4*)(sC2 + col4);
    float4 A3 = *(const float4*)(sA3 + col4);
    float4 C3 = *(const float4*)(sC3 + col4);
    v.x = fmaxf(fmaf(v.x, A2.x, C2.x), 0.f);
    v.y = fmaxf(fmaf(v.y, A2.y, C2.y), 0.f);
    v.z = fmaxf(fmaf(v.z, A2.z, C2.z), 0.f);
    v.w = fmaxf(fmaf(v.w, A2.w, C2.w), 0.f);
    v.x = fmaf(v.x, A3.x, C3.x);
    v.y = fmaf(v.y, A3.y, C3.y);
    v.z = fmaf(v.z, A3.z, C3.z);
    v.w = fmaf(v.w, A3.w, C3.w);
    if (doRelu) {
        v.x = fmaxf(v.x, 0.f); v.y = fmaxf(v.y, 0.f);
        v.z = fmaxf(v.z, 0.f); v.w = fmaxf(v.w, 0.f);
    }
    ((float4*)out)[gid] = v;
}

// ---------------- launch ----------------
extern "C" void kernel_launch(void* const* d_in, const int* in_sizes, int n_in,
                              void* d_out, int out_size)
{
    const float* h_in = (const float*)d_in[0];
    const int*   edges= (const int*)  d_in[1];
    const float* w    = (const float*)d_in[2];
    const float* W0s  = (const float*)d_in[3];
    const float* W1s  = (const float*)d_in[4];
    const float* bn1g = (const float*)d_in[5];
    const float* bn1b = (const float*)d_in[6];
    const float* bn2g = (const float*)d_in[7];
    const float* bn2b = (const float*)d_in[8];
    const float* bn3g = (const float*)d_in[9];
    const float* bn3b = (const float*)d_in[10];
    const int* src = edges;
    const int* dst = edges + EE;

    float *B1, *B2, *sS, *sQ;
    __nv_bfloat16 *bthi, *btlo;
    int *cur;
    int2 *ssw;
    cudaGetSymbolAddress((void**)&B1,   g_B1);
    cudaGetSymbolAddress((void**)&B2,   g_B2);
    cudaGetSymbolAddress((void**)&sS,   g_statS);
    cudaGetSymbolAddress((void**)&sQ,   g_statQ);
    cudaGetSymbolAddress((void**)&bthi, g_bthi);
    cudaGetSymbolAddress((void**)&btlo, g_btlo);
    cudaGetSymbolAddress((void**)&cur,  g_curArr);
    cudaGetSymbolAddress((void**)&ssw,  g_ssw);

    const int GEMM_SMEM = (64 + 64 + 128 + 128) * SMP * 2;   // 104448 B
    cudaFuncSetAttribute(gemm_mma_kernel,
                         cudaFuncAttributeMaxDynamicSharedMemorySize, GEMM_SMEM);

    const int EGRID = (EE + 255) / 256;
    const int SGRID = (6 * DD * DD + 255) / 256;   // 384 (covers NN/256=196 too)
    const int WGRID = (NN * 32 + 255) / 256;       // 6250 (warp per node)

    setup_kernel<<<SGRID, 256>>>(W0s, W1s, bthi, btlo, cur, sS, sQ);
    fill_kernel <<<EGRID, 256>>>(src, dst, w, cur, ssw);

    // Aliasing per layer:
    //   gather: reads h (B2, or h_in layer0) -> writes x (B1)
    //   gemm1 : reads B1 -> writes y (B2)
    //   gemm2 : reads B2 -> writes y2 (B1)
    //   zstats: reads B1
    //   apply : reads B1 -> writes h (B2)   (last layer -> d_out)
    for (int i = 0; i < LL; i++) {
        float *s1 = sS + (i * 3 + 0) * DD, *q1 = sQ + (i * 3 + 0) * DD;
        float *s2 = sS + (i * 3 + 1) * DD, *q2 = sQ + (i * 3 + 1) * DD;
        float *s3 = sS + (i * 3 + 2) * DD, *q3 = sQ + (i * 3 + 2) * DD;

        const float* hsrc = (i == 0) ? h_in : B2;
        gather_kernel<<<WGRID, 256>>>(hsrc, cur, ssw, B1);

        const __nv_bfloat16* b0h = bthi + (i * 2 + 0) * DD * DD;
        const __nv_bfloat16* b0l = btlo + (i * 2 + 0) * DD * DD;
        const __nv_bfloat16* b1h = bthi + (i * 2 + 1) * DD * DD;
        const __nv_bfloat16* b1l = btlo + (i * 2 + 1) * DD * DD;

        gemm_mma_kernel<<<GTILES, 512, GEMM_SMEM>>>(
            B1, b0h, b0l, B2, nullptr, nullptr, nullptr, nullptr, 0, s1, q1);
        gemm_mma_kernel<<<GTILES, 512, GEMM_SMEM>>>(
            B2, b1h, b1l, B1, s1, q1, bn1g + i * DD, bn1b + i * DD, 1, s2, q2);
        zstats_kernel<<<250, 256>>>(B1, s2, q2, bn2g + i * DD, bn2b + i * DD, s3, q3);

        int last = (i == LL - 1);
        apply_kernel<<<WGRID, 256>>>(B1, s2, q2, bn2g + i * DD, bn2b + i * DD,
                                     s3, q3, bn3g + i * DD, bn3b + i * DD,
                                     last ? (float*)d_out : B2, last ? 0 : 1);
    }
}

// round 14
// speedup vs baseline: 1.4121x; 1.4121x over previous
#include <cuda_runtime.h>
#include <cuda_bf16.h>
#include <cstdint>
#include <math.h>

// Problem constants
#define NN 50000
#define EE 600000
#define DD 128
#define LL 3
#define GTILES 782            // ceil(50000/64)
#define NPAD (GTILES * 64)    // 50048
#define SMP 136               // smem row stride (bf16): conflict-free ldmatrix
#define CAP 64                // fixed bucket capacity per node (P(deg>64) ~ 0)

// ---------------- device scratch (static; no runtime alloc) ----------------
__device__ float g_B1[NPAD * DD];   // x  / y2
__device__ float g_B2[NPAD * DD];   // y  / h
__device__ float g_statS[9][DD];    // stage = layer*3 + {gemm1, gemm2, zstats}
__device__ float g_statQ[9][DD];
__device__ __nv_bfloat16 g_bthi[LL * 2 * DD * DD];
__device__ __nv_bfloat16 g_btlo[LL * 2 * DD * DD];
__device__ int  g_curArr[NN];       // slot counter -> degree after fill
__device__ int2 g_ssw[NN * CAP];    // (src, w bits), bucketed per dst

// ---------------- warp-mma helpers ----------------
__device__ __forceinline__ uint32_t smem_u32(const void* p) {
    uint32_t a;
    asm("{ .reg .u64 t; cvta.to.shared.u64 t, %1; cvt.u32.u64 %0, t; }" : "=r"(a) : "l"(p));
    return a;
}
__device__ __forceinline__ void ldsm_x4(uint32_t* r, uint32_t addr) {
    asm volatile("ldmatrix.sync.aligned.m8n8.x4.shared.b16 {%0,%1,%2,%3}, [%4];"
                 : "=r"(r[0]), "=r"(r[1]), "=r"(r[2]), "=r"(r[3]) : "r"(addr));
}
__device__ __forceinline__ void mma_bf16(float* d, const uint32_t* a, const uint32_t* b) {
    asm volatile("mma.sync.aligned.m16n8k16.row.col.f32.bf16.bf16.f32 "
                 "{%0,%1,%2,%3}, {%4,%5,%6,%7}, {%8,%9}, {%0,%1,%2,%3};"
                 : "+f"(d[0]), "+f"(d[1]), "+f"(d[2]), "+f"(d[3])
                 : "r"(a[0]), "r"(a[1]), "r"(a[2]), "r"(a[3]),
                   "r"(b[0]), "r"(b[1]));
}

// BN affine from raw stats: a = g*rsqrt(var+eps), c = b - mean*a
__device__ __forceinline__ void affine_from_stats(
    const float* __restrict__ cs, const float* __restrict__ cq,
    const float* __restrict__ g, const float* __restrict__ b,
    float* sA, float* sC, int t)
{
    if (t < DD) {
        const float invN = 1.f / (float)NN;
        float mean = cs[t] * invN;
        float var  = cq[t] * invN - mean * mean;
        float a = g[t] * rsqrtf(var + 1e-5f);
        sA[t] = a;
        sC[t] = b[t] - mean * a;
    }
}

// ---------------- setup: zero counters/stats + weight hi/lo transpose ----------------
__global__ void setup_kernel(const float* __restrict__ W0s, const float* __restrict__ W1s,
                             __nv_bfloat16* __restrict__ bhi, __nv_bfloat16* __restrict__ blo,
                             int* cur, float* statS, float* statQ)
{
    int idx = blockIdx.x * blockDim.x + threadIdx.x;
    if (idx < NN) cur[idx] = 0;
    if (idx < 9 * DD) { statS[idx] = 0.f; statQ[idx] = 0.f; }
    if (idx < 6 * DD * DD) {
        int m2 = idx >> 14, r = idx & 16383;
        int k = r >> 7, n = r & 127;
        int layer = m2 >> 1, which = m2 & 1;
        const float* W = (which ? W1s : W0s) + layer * DD * DD;
        float v = W[r];
        __nv_bfloat16 h = __float2bfloat16(v);
        __nv_bfloat16 lo = __float2bfloat16(v - __bfloat162float(h));
        bhi[m2 * DD * DD + n * DD + k] = h;
        blo[m2 * DD * DD + n * DD + k] = lo;
    }
}

// Bucketed fill: slot via atomicAdd; no scan needed.
__global__ void fill_kernel(const int* __restrict__ src, const int* __restrict__ dst,
                            const float* __restrict__ w, int* cur, int2* ssw) {
    int e = blockIdx.x * blockDim.x + threadIdx.x;
    if (e >= EE) return;
    int d = __ldg(dst + e);
    int slot = atomicAdd(cur + d, 1);
    if (slot < CAP)
        ssw[d * CAP + slot] = make_int2(__ldg(src + e), __float_as_int(__ldg(w + e)));
}

// x[d] = h[d] + sum_e w*h[src]. Warp per node; 2-way unrolled edge loop.
__global__ void __launch_bounds__(256) gather_kernel(
    const float* __restrict__ hprev, const int* __restrict__ cur,
    const int2* __restrict__ ssw, float* __restrict__ x)
{
    int d = (blockIdx.x * blockDim.x + threadIdx.x) >> 5;
    int l = threadIdx.x & 31;
    if (d >= NN) return;
    int deg = min(__ldg(cur + d), CAP);
    int st  = d * CAP;
    float4 acc0 = *(const float4*)(hprev + (size_t)d * DD + l * 4);
    float4 acc1 = make_float4(0.f, 0.f, 0.f, 0.f);
    int j = 0;
    for (; j + 2 <= deg; j += 2) {
        int2 p0 = __ldg(ssw + st + j);
        int2 p1 = __ldg(ssw + st + j + 1);
        float4 h0 = *(const float4*)(hprev + (size_t)p0.x * DD + l * 4);
        float4 h1 = *(const float4*)(hprev + (size_t)p1.x * DD + l * 4);
        float w0 = __int_as_float(p0.y), w1 = __int_as_float(p1.y);
        acc0.x = fmaf(w0, h0.x, acc0.x); acc1.x = fmaf(w1, h1.x, acc1.x);
        acc0.y = fmaf(w0, h0.y, acc0.y); acc1.y = fmaf(w1, h1.y, acc1.y);
        acc0.z = fmaf(w0, h0.z, acc0.z); acc1.z = fmaf(w1, h1.z, acc1.z);
        acc0.w = fmaf(w0, h0.w, acc0.w); acc1.w = fmaf(w1, h1.w, acc1.w);
    }
    if (j < deg) {
        int2 p = __ldg(ssw + st + j);
        float we = __int_as_float(p.y);
        float4 hv = *(const float4*)(hprev + (size_t)p.x * DD + l * 4);
        acc0.x = fmaf(we, hv.x, acc0.x);
        acc0.y = fmaf(we, hv.y, acc0.y);
        acc0.z = fmaf(we, hv.z, acc0.z);
        acc0.w = fmaf(we, hv.w, acc0.w);
    }
    acc0.x += acc1.x; acc0.y += acc1.y; acc0.z += acc1.z; acc0.w += acc1.w;
    *(float4*)(x + (size_t)d * DD + l * 4) = acc0;
}

// C[64-tile,128] = act(A) @ W, mma.sync bf16 hi/lo 3-pass, fused column stats.
// R10-proven config: 256 threads / 8 warps; warp tile 16(M) x 64(N).
__global__ void __launch_bounds__(256, 2) gemm_mma_kernel(
    const float* __restrict__ A,
    const __nv_bfloat16* __restrict__ Bhi, const __nv_bfloat16* __restrict__ Blo,
    float* __restrict__ C,
    const float* __restrict__ csIn, const float* __restrict__ cqIn,
    const float* __restrict__ bng, const float* __restrict__ bnb, int useAffine,
    float* __restrict__ statS, float* __restrict__ statQ)
{
    extern __shared__ __align__(16) char dyn[];
    __nv_bfloat16* sAhi = (__nv_bfloat16*)dyn;
    __nv_bfloat16* sAlo = sAhi + 64 * SMP;
    __nv_bfloat16* sBhi = sAlo + 64 * SMP;
    __nv_bfloat16* sBlo = sBhi + 128 * SMP;
    __shared__ float colS[DD], colQ[DD];
    __shared__ float sAf[DD], sCf[DD];

    const int t = threadIdx.x, w = t >> 5, l = t & 31;
    const int mBase = blockIdx.x * 64;

    if (t < DD) { colS[t] = 0.f; colQ[t] = 0.f; }
    if (useAffine) {
        affine_from_stats(csIn, cqIn, bng, bnb, sAf, sCf, t);
        __syncthreads();
    }

    float4 aa, cc;
    if (useAffine) { aa = ((const float4*)sAf)[l]; cc = ((const float4*)sCf)[l]; }
#pragma unroll
    for (int it = 0; it < 8; it++) {
        int row = it * 8 + w;
        float4 v = ((const float4*)(A + (size_t)(mBase + row) * DD))[l];
        if (useAffine) {
            v.x = fmaxf(fmaf(v.x, aa.x, cc.x), 0.f);
            v.y = fmaxf(fmaf(v.y, aa.y, cc.y), 0.f);
            v.z = fmaxf(fmaf(v.z, aa.z, cc.z), 0.f);
            v.w = fmaxf(fmaf(v.w, aa.w, cc.w), 0.f);
        }
        __nv_bfloat162 h01 = __floats2bfloat162_rn(v.x, v.y);
        __nv_bfloat162 h23 = __floats2bfloat162_rn(v.z, v.w);
        __nv_bfloat162 l01 = __floats2bfloat162_rn(v.x - __low2float(h01), v.y - __high2float(h01));
        __nv_bfloat162 l23 = __floats2bfloat162_rn(v.z - __low2float(h23), v.w - __high2float(h23));
        int off = row * SMP + l * 4;
        *(uint2*)(sAhi + off) = make_uint2(*(uint32_t*)&h01, *(uint32_t*)&h23);
        *(uint2*)(sAlo + off) = make_uint2(*(uint32_t*)&l01, *(uint32_t*)&l23);
    }
#pragma unroll
    for (int it = 0; it < 16; it++) {
        int row = it * 8 + w;
        uint2 hv = ((const uint2*)(Bhi + (size_t)row * DD))[l];
        uint2 lv = ((const uint2*)(Blo + (size_t)row * DD))[l];
        int off = row * SMP + l * 4;
        *(uint2*)(sBhi + off) = hv;
        *(uint2*)(sBlo + off) = lv;
    }
    __syncthreads();

    const int wm = (w >> 1) * 16;
    const int wn = (w & 1) * 64;
    float acc[8][4];
#pragma unroll
    for (int i = 0; i < 8; i++)
#pragma unroll
        for (int j = 0; j < 4; j++) acc[i][j] = 0.f;

    const int arow = wm + (l & 15);
    const int acol = (l >> 4) << 3;
    const int browb = wn + ((l >> 4) & 1) * 8 + (l & 7);   // paired-n ldsm.x4
    const int bcol  = ((l >> 3) & 1) << 3;

#pragma unroll
    for (int pass = 0; pass < 3; pass++) {
        const __nv_bfloat16* pA = (pass == 2) ? sAlo : sAhi;
        const __nv_bfloat16* pB = (pass == 1) ? sBlo : sBhi;
#pragma unroll
        for (int kc = 0; kc < 8; kc++) {
            const int k0 = kc * 16;
            uint32_t afr[4];
            ldsm_x4(afr, smem_u32(pA + arow * SMP + k0 + acol));
#pragma unroll
            for (int sn2 = 0; sn2 < 4; sn2++) {
                uint32_t bfr[4];
                ldsm_x4(bfr, smem_u32(pB + (browb + sn2 * 16) * SMP + k0 + bcol));
                mma_bf16(acc[sn2 * 2 + 0], afr, bfr + 0);
                mma_bf16(acc[sn2 * 2 + 1], afr, bfr + 2);
            }
        }
    }

    const int g = l >> 2, tq = l & 3;
    const int row0 = mBase + wm + g;
    const float m0 = (row0 < NN) ? 1.f : 0.f;
    const float m1 = (row0 + 8 < NN) ? 1.f : 0.f;
#pragma unroll
    for (int sn = 0; sn < 8; sn++) {
        int col = wn + sn * 8 + tq * 2;
        float* p0 = C + (size_t)row0 * DD + col;
        *(float2*)p0            = make_float2(acc[sn][0], acc[sn][1]);
        *(float2*)(p0 + 8 * DD) = make_float2(acc[sn][2], acc[sn][3]);
        float v0 = m0 * acc[sn][0], v1 = m0 * acc[sn][1];
        float v2 = m1 * acc[sn][2], v3 = m1 * acc[sn][3];
        float cs0 = v0 + v2, cs1 = v1 + v3;
        float cq0 = v0 * v0 + v2 * v2, cq1 = v1 * v1 + v3 * v3;
#pragma unroll
        for (int dlt = 16; dlt >= 4; dlt >>= 1) {
            cs0 += __shfl_down_sync(0xffffffffu, cs0, dlt);
            cs1 += __shfl_down_sync(0xffffffffu, cs1, dlt);
            cq0 += __shfl_down_sync(0xffffffffu, cq0, dlt);
            cq1 += __shfl_down_sync(0xffffffffu, cq1, dlt);
        }
        if (l < 4) {
            int c0 = wn + sn * 8 + l * 2;
            atomicAdd(&colS[c0], cs0);  atomicAdd(&colS[c0 + 1], cs1);
            atomicAdd(&colQ[c0], cq0);  atomicAdd(&colQ[c0 + 1], cq1);
        }
    }
    __syncthreads();
    if (t < DD) {
        atomicAdd(statS + t, colS[t]);
        atomicAdd(statQ + t, colQ[t]);
    }
}

// stats of relu(bn2(y2)); bn2 affine from raw stats at entry.
__global__ void __launch_bounds__(256) zstats_kernel(const float* __restrict__ y2,
                                                     const float* __restrict__ cs2,
                                                     const float* __restrict__ cq2,
                                                     const float* __restrict__ bn2g,
                                                     const float* __restrict__ bn2b,
                                                     float* __restrict__ cs,
                                                     float* __restrict__ cq)
{
    __shared__ float shS[8][DD];
    __shared__ float shQ[8][DD];
    __shared__ float sAf[DD], sCf[DD];
    const int t = threadIdx.x;
    const int c4 = (t & 31) * 4;
    const int rg = t >> 5;
    affine_from_stats(cs2, cq2, bn2g, bn2b, sAf, sCf, t);
    __syncthreads();
    float4 a = *(const float4*)(sAf + c4);
    float4 c = *(const float4*)(sCf + c4);
    float4 s = make_float4(0.f, 0.f, 0.f, 0.f), q = make_float4(0.f, 0.f, 0.f, 0.f);
    for (int m = blockIdx.x * 8 + rg; m < NN; m += gridDim.x * 8) {
        float4 v = *(const float4*)(y2 + (size_t)m * DD + c4);
        v.x = fmaxf(fmaf(v.x, a.x, c.x), 0.f);
        v.y = fmaxf(fmaf(v.y, a.y, c.y), 0.f);
        v.z = fmaxf(fmaf(v.z, a.z, c.z), 0.f);
        v.w = fmaxf(fmaf(v.w, a.w, c.w), 0.f);
        s.x += v.x; s.y += v.y; s.z += v.z; s.w += v.w;
        q.x += v.x * v.x; q.y += v.y * v.y; q.z += v.z * v.z; q.w += v.w * v.w;
    }
    *(float4*)&shS[rg][c4] = s;
    *(float4*)&shQ[rg][c4] = q;
    __syncthreads();
    if (t < DD) {
        float ts = 0.f, tqv = 0.f;
#pragma unroll
        for (int i = 0; i < 8; i++) { ts += shS[i][t]; tqv += shQ[i][t]; }
        atomicAdd(cs + t, ts);
        atomicAdd(cq + t, tqv);
    }
}

// out = bn3(relu(bn2(y2))) (+ optional relu). Affines from raw stats at entry.
__global__ void __launch_bounds__(256) apply_kernel(
    const float* __restrict__ y2,
    const float* __restrict__ cs2, const float* __restrict__ cq2,
    const float* __restrict__ bn2g, const float* __restrict__ bn2b,
    const float* __restrict__ cs3, const float* __restrict__ cq3,
    const float* __restrict__ bn3g, const float* __restrict__ bn3b,
    float* __restrict__ out, int doRelu)
{
    __shared__ float sA2[DD], sC2[DD], sA3[DD], sC3[DD];
    const int t = threadIdx.x;
    affine_from_stats(cs2, cq2, bn2g, bn2b, sA2, sC2, t);
    affine_from_stats(cs3, cq3, bn3g, bn3b, sA3, sC3, t);
    __syncthreads();
    int gid = blockIdx.x * blockDim.x + t;
    if (gid >= NN * (DD / 4)) return;
    int col4 = (gid & (DD / 4 - 1)) << 2;
    float4 v = ((const float4*)y2)[gid];
    float4 A2 = *(const float4*)(sA2 + col4);
    float4 C2 = *(const float4*)(sC2 + col4);
    float4 A3 = *(const float4*)(sA3 + col4);
    float4 C3 = *(const float4*)(sC3 + col4);
    v.x = fmaxf(fmaf(v.x, A2.x, C2.x), 0.f);
    v.y = fmaxf(fmaf(v.y, A2.y, C2.y), 0.f);
    v.z = fmaxf(fmaf(v.z, A2.z, C2.z), 0.f);
    v.w = fmaxf(fmaf(v.w, A2.w, C2.w), 0.f);
    v.x = fmaf(v.x, A3.x, C3.x);
    v.y = fmaf(v.y, A3.y, C3.y);
    v.z = fmaf(v.z, A3.z, C3.z);
    v.w = fmaf(v.w, A3.w, C3.w);
    if (doRelu) {
        v.x = fmaxf(v.x, 0.f); v.y = fmaxf(v.y, 0.f);
        v.z = fmaxf(v.z, 0.f); v.w = fmaxf(v.w, 0.f);
    }
    ((float4*)out)[gid] = v;
}

// ---------------- launch ----------------
extern "C" void kernel_launch(void* const* d_in, const int* in_sizes, int n_in,
                              void* d_out, int out_size)
{
    const float* h_in = (const float*)d_in[0];
    const int*   edges= (const int*)  d_in[1];
    const float* w    = (const float*)d_in[2];
    const float* W0s  = (const float*)d_in[3];
    const float* W1s  = (const float*)d_in[4];
    const float* bn1g = (const float*)d_in[5];
    const float* bn1b = (const float*)d_in[6];
    const float* bn2g = (const float*)d_in[7];
    const float* bn2b = (const float*)d_in[8];
    const float* bn3g = (const float*)d_in[9];
    const float* bn3b = (const float*)d_in[10];
    const int* src = edges;
    const int* dst = edges + EE;

    float *B1, *B2, *sS, *sQ;
    __nv_bfloat16 *bthi, *btlo;
    int *cur;
    int2 *ssw;
    cudaGetSymbolAddress((void**)&B1,   g_B1);
    cudaGetSymbolAddress((void**)&B2,   g_B2);
    cudaGetSymbolAddress((void**)&sS,   g_statS);
    cudaGetSymbolAddress((void**)&sQ,   g_statQ);
    cudaGetSymbolAddress((void**)&bthi, g_bthi);
    cudaGetSymbolAddress((void**)&btlo, g_btlo);
    cudaGetSymbolAddress((void**)&cur,  g_curArr);
    cudaGetSymbolAddress((void**)&ssw,  g_ssw);

    const int GEMM_SMEM = (64 + 64 + 128 + 128) * SMP * 2;   // 104448 B
    cudaFuncSetAttribute(gemm_mma_kernel,
                         cudaFuncAttributeMaxDynamicSharedMemorySize, GEMM_SMEM);

    const int EGRID = (EE + 255) / 256;
    const int SGRID = (6 * DD * DD + 255) / 256;   // 384 (covers NN/256=196 too)
    const int WGRID = (NN * 32 + 255) / 256;       // 6250 (warp per node)

    setup_kernel<<<SGRID, 256>>>(W0s, W1s, bthi, btlo, cur, sS, sQ);
    fill_kernel <<<EGRID, 256>>>(src, dst, w, cur, ssw);

    // Aliasing per layer:
    //   gather: reads h (B2, or h_in layer0) -> writes x (B1)
    //   gemm1 : reads B1 -> writes y (B2)
    //   gemm2 : reads B2 -> writes y2 (B1)
    //   zstats: reads B1
    //   apply : reads B1 -> writes h (B2)   (last layer -> d_out)
    for (int i = 0; i < LL; i++) {
        float *s1 = sS + (i * 3 + 0) * DD, *q1 = sQ + (i * 3 + 0) * DD;
        float *s2 = sS + (i * 3 + 1) * DD, *q2 = sQ + (i * 3 + 1) * DD;
        float *s3 = sS + (i * 3 + 2) * DD, *q3 = sQ + (i * 3 + 2) * DD;

        const float* hsrc = (i == 0) ? h_in : B2;
        gather_kernel<<<WGRID, 256>>>(hsrc, cur, ssw, B1);

        const __nv_bfloat16* b0h = bthi + (i * 2 + 0) * DD * DD;
        const __nv_bfloat16* b0l = btlo + (i * 2 + 0) * DD * DD;
        const __nv_bfloat16* b1h = bthi + (i * 2 + 1) * DD * DD;
        const __nv_bfloat16* b1l = btlo + (i * 2 + 1) * DD * DD;

        gemm_mma_kernel<<<GTILES, 256, GEMM_SMEM>>>(
            B1, b0h, b0l, B2, nullptr, nullptr, nullptr, nullptr, 0, s1, q1);
        gemm_mma_kernel<<<GTILES, 256, GEMM_SMEM>>>(
            B2, b1h, b1l, B1, s1, q1, bn1g + i * DD, bn1b + i * DD, 1, s2, q2);
        zstats_kernel<<<250, 256>>>(B1, s2, q2, bn2g + i * DD, bn2b + i * DD, s3, q3);

        int last = (i == LL - 1);
        apply_kernel<<<WGRID, 256>>>(B1, s2, q2, bn2g + i * DD, bn2b + i * DD,
                                     s3, q3, bn3g + i * DD, bn3b + i * DD,
                                     last ? (float*)d_out : B2, last ? 0 : 1);
    }
}

// round 15
// speedup vs baseline: 1.5637x; 1.1074x over previous
#include <cuda_runtime.h>
#include <cuda_bf16.h>
#include <cstdint>
#include <math.h>

// Problem constants
#define NN 50000
#define EE 600000
#define DD 128
#define LL 3
#define GTILES 391            // ceil(50000/128)
#define NPAD (GTILES * 128)   // 50048
#define SMP 136               // smem row stride (bf16): conflict-free ldmatrix
#define CAP 64                // fixed bucket capacity per node (P(deg>64) ~ 0)

// ---------------- device scratch (static; no runtime alloc) ----------------
__device__ float g_B1[NPAD * DD];   // x  / y2
__device__ float g_B2[NPAD * DD];   // y  / h
__device__ float g_statS[9][DD];
__device__ float g_statQ[9][DD];
__device__ __nv_bfloat16 g_bthi[LL * 2 * DD * DD];
__device__ __nv_bfloat16 g_btlo[LL * 2 * DD * DD];
__device__ int  g_curArr[NN];
__device__ int2 g_ssw[NN * CAP];

// ---------------- warp-mma helpers ----------------
__device__ __forceinline__ uint32_t smem_u32(const void* p) {
    uint32_t a;
    asm("{ .reg .u64 t; cvta.to.shared.u64 t, %1; cvt.u32.u64 %0, t; }" : "=r"(a) : "l"(p));
    return a;
}
__device__ __forceinline__ void ldsm_x4(uint32_t* r, uint32_t addr) {
    asm volatile("ldmatrix.sync.aligned.m8n8.x4.shared.b16 {%0,%1,%2,%3}, [%4];"
                 : "=r"(r[0]), "=r"(r[1]), "=r"(r[2]), "=r"(r[3]) : "r"(addr));
}
__device__ __forceinline__ void mma_bf16(float* d, const uint32_t* a, const uint32_t* b) {
    asm volatile("mma.sync.aligned.m16n8k16.row.col.f32.bf16.bf16.f32 "
                 "{%0,%1,%2,%3}, {%4,%5,%6,%7}, {%8,%9}, {%0,%1,%2,%3};"
                 : "+f"(d[0]), "+f"(d[1]), "+f"(d[2]), "+f"(d[3])
                 : "r"(a[0]), "r"(a[1]), "r"(a[2]), "r"(a[3]),
                   "r"(b[0]), "r"(b[1]));
}

// BN affine from raw stats: a = g*rsqrt(var+eps), c = b - mean*a
__device__ __forceinline__ void affine_from_stats(
    const float* __restrict__ cs, const float* __restrict__ cq,
    const float* __restrict__ g, const float* __restrict__ b,
    float* sA, float* sC, int t)
{
    if (t < DD) {
        const float invN = 1.f / (float)NN;
        float mean = cs[t] * invN;
        float var  = cq[t] * invN - mean * mean;
        float a = g[t] * rsqrtf(var + 1e-5f);
        sA[t] = a;
        sC[t] = b[t] - mean * a;
    }
}

// ---------------- setup: zero counters/stats + weight hi/lo transpose ----------------
__global__ void setup_kernel(const float* __restrict__ W0s, const float* __restrict__ W1s,
                             __nv_bfloat16* __restrict__ bhi, __nv_bfloat16* __restrict__ blo,
                             int* cur, float* statS, float* statQ)
{
    int idx = blockIdx.x * blockDim.x + threadIdx.x;
    if (idx < NN) cur[idx] = 0;
    if (idx < 9 * DD) { statS[idx] = 0.f; statQ[idx] = 0.f; }
    if (idx < 6 * DD * DD) {
        int m2 = idx >> 14, r = idx & 16383;
        int k = r >> 7, n = r & 127;
        int layer = m2 >> 1, which = m2 & 1;
        const float* W = (which ? W1s : W0s) + layer * DD * DD;
        float v = W[r];
        __nv_bfloat16 h = __float2bfloat16(v);
        __nv_bfloat16 lo = __float2bfloat16(v - __bfloat162float(h));
        bhi[m2 * DD * DD + n * DD + k] = h;
        blo[m2 * DD * DD + n * DD + k] = lo;
    }
}

// Bucketed fill: slot via atomicAdd; no scan needed.
__global__ void fill_kernel(const int* __restrict__ src, const int* __restrict__ dst,
                            const float* __restrict__ w, int* cur, int2* ssw) {
    int e = blockIdx.x * blockDim.x + threadIdx.x;
    if (e >= EE) return;
    int d = __ldg(dst + e);
    int slot = atomicAdd(cur + d, 1);
    if (slot < CAP)
        ssw[d * CAP + slot] = make_int2(__ldg(src + e), __float_as_int(__ldg(w + e)));
}

// x[d] = h[d] + sum_e w*h[src]. Warp per node; 2-way unrolled edge loop.
__global__ void __launch_bounds__(256) gather_kernel(
    const float* __restrict__ hprev, const int* __restrict__ cur,
    const int2* __restrict__ ssw, float* __restrict__ x)
{
    int d = (blockIdx.x * blockDim.x + threadIdx.x) >> 5;
    int l = threadIdx.x & 31;
    if (d >= NN) return;
    int deg = min(__ldg(cur + d), CAP);
    int st  = d * CAP;
    float4 acc0 = *(const float4*)(hprev + (size_t)d * DD + l * 4);
    float4 acc1 = make_float4(0.f, 0.f, 0.f, 0.f);
    int j = 0;
    for (; j + 2 <= deg; j += 2) {
        int2 p0 = __ldg(ssw + st + j);
        int2 p1 = __ldg(ssw + st + j + 1);
        float4 h0 = *(const float4*)(hprev + (size_t)p0.x * DD + l * 4);
        float4 h1 = *(const float4*)(hprev + (size_t)p1.x * DD + l * 4);
        float w0 = __int_as_float(p0.y), w1 = __int_as_float(p1.y);
        acc0.x = fmaf(w0, h0.x, acc0.x); acc1.x = fmaf(w1, h1.x, acc1.x);
        acc0.y = fmaf(w0, h0.y, acc0.y); acc1.y = fmaf(w1, h1.y, acc1.y);
        acc0.z = fmaf(w0, h0.z, acc0.z); acc1.z = fmaf(w1, h1.z, acc1.z);
        acc0.w = fmaf(w0, h0.w, acc0.w); acc1.w = fmaf(w1, h1.w, acc1.w);
    }
    if (j < deg) {
        int2 p = __ldg(ssw + st + j);
        float we = __int_as_float(p.y);
        float4 hv = *(const float4*)(hprev + (size_t)p.x * DD + l * 4);
        acc0.x = fmaf(we, hv.x, acc0.x);
        acc0.y = fmaf(we, hv.y, acc0.y);
        acc0.z = fmaf(we, hv.z, acc0.z);
        acc0.w = fmaf(we, hv.w, acc0.w);
    }
    acc0.x += acc1.x; acc0.y += acc1.y; acc0.z += acc1.z; acc0.w += acc1.w;
    *(float4*)(x + (size_t)d * DD + l * 4) = acc0;
}

// C[128-tile,128] = act(A) @ W, mma.sync bf16 hi/lo 3-pass, fused column stats.
// R3-proven geometry: 256 thr / 8 warps; warp tile 32(M) x 64(N); 139 KB smem.
__global__ void __launch_bounds__(256) gemm_mma_kernel(
    const float* __restrict__ A,
    const __nv_bfloat16* __restrict__ Bhi, const __nv_bfloat16* __restrict__ Blo,
    float* __restrict__ C,
    const float* __restrict__ csIn, const float* __restrict__ cqIn,
    const float* __restrict__ bng, const float* __restrict__ bnb, int useAffine,
    float* __restrict__ statS, float* __restrict__ statQ)
{
    extern __shared__ __align__(16) char dyn[];
    __nv_bfloat16* sAhi = (__nv_bfloat16*)dyn;
    __nv_bfloat16* sAlo = sAhi + 128 * SMP;
    __nv_bfloat16* sBhi = sAlo + 128 * SMP;
    __nv_bfloat16* sBlo = sBhi + 128 * SMP;
    __shared__ float colS[DD], colQ[DD];
    __shared__ float sAf[DD], sCf[DD];

    const int t = threadIdx.x, w = t >> 5, l = t & 31;
    const int mBase = blockIdx.x * 128;

    if (t < DD) { colS[t] = 0.f; colQ[t] = 0.f; }
    if (useAffine) {
        affine_from_stats(csIn, cqIn, bng, bnb, sAf, sCf, t);
        __syncthreads();
    }

    // stage A: 128 rows fp32 -> (affine+relu) -> bf16 hi/lo
    float4 aa, cc;
    if (useAffine) { aa = ((const float4*)sAf)[l]; cc = ((const float4*)sCf)[l]; }
#pragma unroll
    for (int it = 0; it < 16; it++) {
        int row = it * 8 + w;
        float4 v = ((const float4*)(A + (size_t)(mBase + row) * DD))[l];
        if (useAffine) {
            v.x = fmaxf(fmaf(v.x, aa.x, cc.x), 0.f);
            v.y = fmaxf(fmaf(v.y, aa.y, cc.y), 0.f);
            v.z = fmaxf(fmaf(v.z, aa.z, cc.z), 0.f);
            v.w = fmaxf(fmaf(v.w, aa.w, cc.w), 0.f);
        }
        __nv_bfloat162 h01 = __floats2bfloat162_rn(v.x, v.y);
        __nv_bfloat162 h23 = __floats2bfloat162_rn(v.z, v.w);
        __nv_bfloat162 l01 = __floats2bfloat162_rn(v.x - __low2float(h01), v.y - __high2float(h01));
        __nv_bfloat162 l23 = __floats2bfloat162_rn(v.z - __low2float(h23), v.w - __high2float(h23));
        int off = row * SMP + l * 4;
        *(uint2*)(sAhi + off) = make_uint2(*(uint32_t*)&h01, *(uint32_t*)&h23);
        *(uint2*)(sAlo + off) = make_uint2(*(uint32_t*)&l01, *(uint32_t*)&l23);
    }
    // stage B: 128 n-rows, pre-split bf16 W^T[n][k]
#pragma unroll
    for (int it = 0; it < 16; it++) {
        int row = it * 8 + w;
        uint2 hv = ((const uint2*)(Bhi + (size_t)row * DD))[l];
        uint2 lv = ((const uint2*)(Blo + (size_t)row * DD))[l];
        int off = row * SMP + l * 4;
        *(uint2*)(sBhi + off) = hv;
        *(uint2*)(sBlo + off) = lv;
    }
    __syncthreads();

    // warp tile: 32(M) x 64(N); 2 m-subtiles x 8 n-subtiles
    const int wm = (w >> 1) * 32;
    const int wn = (w & 1) * 64;
    float acc[2][8][4];
#pragma unroll
    for (int s = 0; s < 2; s++)
#pragma unroll
        for (int i = 0; i < 8; i++)
#pragma unroll
            for (int j = 0; j < 4; j++) acc[s][i][j] = 0.f;

    const int arow = l & 15;
    const int acol = (l >> 4) << 3;
    const int browb = wn + ((l >> 4) & 1) * 8 + (l & 7);   // paired-n ldsm.x4
    const int bcol  = ((l >> 3) & 1) << 3;

#pragma unroll
    for (int pass = 0; pass < 3; pass++) {
        const __nv_bfloat16* pA = (pass == 2) ? sAlo : sAhi;
        const __nv_bfloat16* pB = (pass == 1) ? sBlo : sBhi;
#pragma unroll
        for (int kc = 0; kc < 8; kc++) {
            const int k0 = kc * 16;
            uint32_t afr[2][4];
#pragma unroll
            for (int sm = 0; sm < 2; sm++)
                ldsm_x4(afr[sm], smem_u32(pA + (wm + sm * 16 + arow) * SMP + k0 + acol));
#pragma unroll
            for (int sn2 = 0; sn2 < 4; sn2++) {
                uint32_t bfr[4];
                ldsm_x4(bfr, smem_u32(pB + (browb + sn2 * 16) * SMP + k0 + bcol));
#pragma unroll
                for (int sm = 0; sm < 2; sm++) {
                    mma_bf16(acc[sm][sn2 * 2 + 0], afr[sm], bfr + 0);
                    mma_bf16(acc[sm][sn2 * 2 + 1], afr[sm], bfr + 2);
                }
            }
        }
    }

    // epilogue: store + fused column stats (mask pad rows)
    const int g = l >> 2, tq = l & 3;
#pragma unroll
    for (int sm = 0; sm < 2; sm++) {
        const int row0 = mBase + wm + sm * 16 + g;
        const float m0 = (row0 < NN) ? 1.f : 0.f;
        const float m1 = (row0 + 8 < NN) ? 1.f : 0.f;
#pragma unroll
        for (int sn = 0; sn < 8; sn++) {
            int col = wn + sn * 8 + tq * 2;
            float* p0 = C + (size_t)row0 * DD + col;
            *(float2*)p0            = make_float2(acc[sm][sn][0], acc[sm][sn][1]);
            *(float2*)(p0 + 8 * DD) = make_float2(acc[sm][sn][2], acc[sm][sn][3]);
            float v0 = m0 * acc[sm][sn][0], v1 = m0 * acc[sm][sn][1];
            float v2 = m1 * acc[sm][sn][2], v3 = m1 * acc[sm][sn][3];
            float cs0 = v0 + v2, cs1 = v1 + v3;
            float cq0 = v0 * v0 + v2 * v2, cq1 = v1 * v1 + v3 * v3;
#pragma unroll
            for (int dlt = 16; dlt >= 4; dlt >>= 1) {
                cs0 += __shfl_down_sync(0xffffffffu, cs0, dlt);
                cs1 += __shfl_down_sync(0xffffffffu, cs1, dlt);
                cq0 += __shfl_down_sync(0xffffffffu, cq0, dlt);
                cq1 += __shfl_down_sync(0xffffffffu, cq1, dlt);
            }
            if (l < 4) {
                int c0 = wn + sn * 8 + l * 2;
                atomicAdd(&colS[c0], cs0);  atomicAdd(&colS[c0 + 1], cs1);
                atomicAdd(&colQ[c0], cq0);  atomicAdd(&colQ[c0 + 1], cq1);
            }
        }
    }
    __syncthreads();
    if (t < DD) {
        atomicAdd(statS + t, colS[t]);
        atomicAdd(statQ + t, colQ[t]);
    }
}

// stats of relu(bn2(y2)); bn2 affine from raw stats at entry.
__global__ void __launch_bounds__(256) zstats_kernel(const float* __restrict__ y2,
                                                     const float* __restrict__ cs2,
                                                     const float* __restrict__ cq2,
                                                     const float* __restrict__ bn2g,
                                                     const float* __restrict__ bn2b,
                                                     float* __restrict__ cs,
                                                     float* __restrict__ cq)
{
    __shared__ float shS[8][DD];
    __shared__ float shQ[8][DD];
    __shared__ float sAf[DD], sCf[DD];
    const int t = threadIdx.x;
    const int c4 = (t & 31) * 4;
    const int rg = t >> 5;
    affine_from_stats(cs2, cq2, bn2g, bn2b, sAf, sCf, t);
    __syncthreads();
    float4 a = *(const float4*)(sAf + c4);
    float4 c = *(const float4*)(sCf + c4);
    float4 s = make_float4(0.f, 0.f, 0.f, 0.f), q = make_float4(0.f, 0.f, 0.f, 0.f);
    for (int m = blockIdx.x * 8 + rg; m < NN; m += gridDim.x * 8) {
        float4 v = *(const float4*)(y2 + (size_t)m * DD + c4);
        v.x = fmaxf(fmaf(v.x, a.x, c.x), 0.f);
        v.y = fmaxf(fmaf(v.y, a.y, c.y), 0.f);
        v.z = fmaxf(fmaf(v.z, a.z, c.z), 0.f);
        v.w = fmaxf(fmaf(v.w, a.w, c.w), 0.f);
        s.x += v.x; s.y += v.y; s.z += v.z; s.w += v.w;
        q.x += v.x * v.x; q.y += v.y * v.y; q.z += v.z * v.z; q.w += v.w * v.w;
    }
    *(float4*)&shS[rg][c4] = s;
    *(float4*)&shQ[rg][c4] = q;
    __syncthreads();
    if (t < DD) {
        float ts = 0.f, tqv = 0.f;
#pragma unroll
        for (int i = 0; i < 8; i++) { ts += shS[i][t]; tqv += shQ[i][t]; }
        atomicAdd(cs + t, ts);
        atomicAdd(cq + t, tqv);
    }
}

// out = bn3(relu(bn2(y2))) (+ optional relu). Affines from raw stats at entry.
__global__ void __launch_bounds__(256) apply_kernel(
    const float* __restrict__ y2,
    const float* __restrict__ cs2, const float* __restrict__ cq2,
    const float* __restrict__ bn2g, const float* __restrict__ bn2b,
    const float* __restrict__ cs3, const float* __restrict__ cq3,
    const float* __restrict__ bn3g, const float* __restrict__ bn3b,
    float* __restrict__ out, int doRelu)
{
    __shared__ float sA2[DD], sC2[DD], sA3[DD], sC3[DD];
    const int t = threadIdx.x;
    affine_from_stats(cs2, cq2, bn2g, bn2b, sA2, sC2, t);
    affine_from_stats(cs3, cq3, bn3g, bn3b, sA3, sC3, t);
    __syncthreads();
    int gid = blockIdx.x * blockDim.x + t;
    if (gid >= NN * (DD / 4)) return;
    int col4 = (gid & (DD / 4 - 1)) << 2;
    float4 v = ((const float4*)y2)[gid];
    float4 A2 = *(const float4*)(sA2 + col4);
    float4 C2 = *(const float4*)(sC2 + col4);
    float4 A3 = *(const float4*)(sA3 + col4);
    float4 C3 = *(const float4*)(sC3 + col4);
    v.x = fmaxf(fmaf(v.x, A2.x, C2.x), 0.f);
    v.y = fmaxf(fmaf(v.y, A2.y, C2.y), 0.f);
    v.z = fmaxf(fmaf(v.z, A2.z, C2.z), 0.f);
    v.w = fmaxf(fmaf(v.w, A2.w, C2.w), 0.f);
    v.x = fmaf(v.x, A3.x, C3.x);
    v.y = fmaf(v.y, A3.y, C3.y);
    v.z = fmaf(v.z, A3.z, C3.z);
    v.w = fmaf(v.w, A3.w, C3.w);
    if (doRelu) {
        v.x = fmaxf(v.x, 0.f); v.y = fmaxf(v.y, 0.f);
        v.z = fmaxf(v.z, 0.f); v.w = fmaxf(v.w, 0.f);
    }
    ((float4*)out)[gid] = v;
}

// ---------------- launch ----------------
extern "C" void kernel_launch(void* const* d_in, const int* in_sizes, int n_in,
                              void* d_out, int out_size)
{
    const float* h_in = (const float*)d_in[0];
    const int*   edges= (const int*)  d_in[1];
    const float* w    = (const float*)d_in[2];
    const float* W0s  = (const float*)d_in[3];
    const float* W1s  = (const float*)d_in[4];
    const float* bn1g = (const float*)d_in[5];
    const float* bn1b = (const float*)d_in[6];
    const float* bn2g = (const float*)d_in[7];
    const float* bn2b = (const float*)d_in[8];
    const float* bn3g = (const float*)d_in[9];
    const float* bn3b = (const float*)d_in[10];
    const int* src = edges;
    const int* dst = edges + EE;

    float *B1, *B2, *sS, *sQ;
    __nv_bfloat16 *bthi, *btlo;
    int *cur;
    int2 *ssw;
    cudaGetSymbolAddress((void**)&B1,   g_B1);
    cudaGetSymbolAddress((void**)&B2,   g_B2);
    cudaGetSymbolAddress((void**)&sS,   g_statS);
    cudaGetSymbolAddress((void**)&sQ,   g_statQ);
    cudaGetSymbolAddress((void**)&bthi, g_bthi);
    cudaGetSymbolAddress((void**)&btlo, g_btlo);
    cudaGetSymbolAddress((void**)&cur,  g_curArr);
    cudaGetSymbolAddress((void**)&ssw,  g_ssw);

    const int GEMM_SMEM = 4 * 128 * SMP * 2;   // 139264 B
    cudaFuncSetAttribute(gemm_mma_kernel,
                         cudaFuncAttributeMaxDynamicSharedMemorySize, GEMM_SMEM);

    const int EGRID = (EE + 255) / 256;
    const int SGRID = (6 * DD * DD + 255) / 256;   // 384
    const int WGRID = (NN * 32 + 255) / 256;       // 6250 (warp per node)

    setup_kernel<<<SGRID, 256>>>(W0s, W1s, bthi, btlo, cur, sS, sQ);
    fill_kernel <<<EGRID, 256>>>(src, dst, w, cur, ssw);

    // Aliasing per layer:
    //   gather: reads h (B2, or h_in layer0) -> writes x (B1)
    //   gemm1 : reads B1 -> writes y (B2)
    //   gemm2 : reads B2 -> writes y2 (B1)
    //   zstats: reads B1
    //   apply : reads B1 -> writes h (B2)   (last layer -> d_out)
    for (int i = 0; i < LL; i++) {
        float *s1 = sS + (i * 3 + 0) * DD, *q1 = sQ + (i * 3 + 0) * DD;
        float *s2 = sS + (i * 3 + 1) * DD, *q2 = sQ + (i * 3 + 1) * DD;
        float *s3 = sS + (i * 3 + 2) * DD, *q3 = sQ + (i * 3 + 2) * DD;

        const float* hsrc = (i == 0) ? h_in : B2;
        gather_kernel<<<WGRID, 256>>>(hsrc, cur, ssw, B1);

        const __nv_bfloat16* b0h = bthi + (i * 2 + 0) * DD * DD;
        const __nv_bfloat16* b0l = btlo + (i * 2 + 0) * DD * DD;
        const __nv_bfloat16* b1h = bthi + (i * 2 + 1) * DD * DD;
        const __nv_bfloat16* b1l = btlo + (i * 2 + 1) * DD * DD;

        gemm_mma_kernel<<<GTILES, 256, GEMM_SMEM>>>(
            B1, b0h, b0l, B2, nullptr, nullptr, nullptr, nullptr, 0, s1, q1);
        gemm_mma_kernel<<<GTILES, 256, GEMM_SMEM>>>(
            B2, b1h, b1l, B1, s1, q1, bn1g + i * DD, bn1b + i * DD, 1, s2, q2);
        zstats_kernel<<<250, 256>>>(B1, s2, q2, bn2g + i * DD, bn2b + i * DD, s3, q3);

        int last = (i == LL - 1);
        apply_kernel<<<WGRID, 256>>>(B1, s2, q2, bn2g + i * DD, bn2b + i * DD,
                                     s3, q3, bn3g + i * DD, bn3b + i * DD,
                                     last ? (float*)d_out : B2, last ? 0 : 1);
    }
}